// round 11
// baseline (speedup 1.0000x reference)
#include <cuda_runtime.h>
#include <cstdint>

// LSTM B=4096 T=256 I=8 H=32 O=1.
// Two-warp k-split cooperative design:
//  - CTA = 64 thr = 2 warps = 4 batch sequences; grid = 1024 (<=7 CTAs/SM).
//  - lane j = hidden unit j. Warp 0: k=0..15, i=0..3; warp 1: k=16..31, i=4..7.
//  - Weights as NATURAL gate pairs {wi,wf}/{wg,wo} in registers: only 64+16
//    u64-regs of weights per thread -> no spill, 13.8 warps/SM.
//  - h and x stored DUPLICATED ({v,v} u64) in smem -> broadcast LDS multiplier.
//  - Per step: each warp computes partial z for all 4 batches over its k/i
//    range; halves exchanged via smem; warp w finishes activations for
//    batches {2w, 2w+1} and writes duplicated h.
//  - tanh.approx activations; sigmoid 0.5 scale folded into i,f,o weights.

#define B_TOT 4096
#define T_TOT 256
#define I_SZ 8
#define CHUNK 16
#define NCHUNK (T_TOT / CHUNK)

typedef unsigned long long u64;

__device__ __forceinline__ u64 pack2(float a, float b) {
    u64 r; asm("mov.b64 %0,{%1,%2};" : "=l"(r) : "f"(a), "f"(b)); return r;
}
__device__ __forceinline__ void unpack2(u64 v, float& a, float& b) {
    asm("mov.b64 {%0,%1},%2;" : "=f"(a), "=f"(b) : "l"(v));
}
__device__ __forceinline__ u64 fma2(u64 a, u64 b, u64 c) {
    u64 d; asm("fma.rn.f32x2 %0,%1,%2,%3;" : "=l"(d) : "l"(a), "l"(b), "l"(c)); return d;
}
__device__ __forceinline__ u64 add2(u64 a, u64 b) {
    u64 d; asm("add.rn.f32x2 %0,%1,%2;" : "=l"(d) : "l"(a), "l"(b)); return d;
}
__device__ __forceinline__ float tanhap(float x) {
    float y; asm("tanh.approx.f32 %0,%1;" : "=f"(y) : "f"(x)); return y;
}
// i,f,o pre-scaled by 0.5: sigmoid(z) = 0.5*tanh(z/2) + 0.5
__device__ __forceinline__ float sig_h(float zhalf) {
    return fmaf(0.5f, tanhap(zhalf), 0.5f);
}

__global__ void __launch_bounds__(64, 7)
lstm_kernel(const float* __restrict__ x,
            const float* __restrict__ W_ih,
            const float* __restrict__ W_hh,
            const float* __restrict__ b_ih,
            const float* __restrict__ b_hh,
            const float* __restrict__ W_out,
            const float* __restrict__ b_out,
            float* __restrict__ out)
{
    // all u64 entries below are {v,v} duplicated pairs unless noted
    __shared__ __align__(16) u64 x_sm[CHUNK * I_SZ * 4];  // cell (t*8+i)*4 + b
    __shared__ __align__(16) u64 hA_sm[32 * 2];           // k -> {h0,h0},{h1,h1}
    __shared__ __align__(16) u64 hB_sm[32 * 2];           // k -> {h2,h2},{h3,h3}
    __shared__ __align__(16) u64 ex_if[2 * 32 * 2];       // partial z exchange (gate pairs)
    __shared__ __align__(16) u64 ex_go[2 * 32 * 2];

    const int lane = threadIdx.x & 31;
    const int w    = threadIdx.x >> 5;      // 0 or 1
    const int koff = w * 16;
    const int ioff = w * 4;

    // ---- W_hh k-slice -> registers as natural gate pairs (i,f,o x0.5) ----
    u64 wif[16], wgo[16];
#pragma unroll
    for (int kk = 0; kk < 16; ++kk) {
        const int k = koff + kk;
        wif[kk] = pack2(0.5f * W_hh[(0 * 32 + lane) * 32 + k],
                        0.5f * W_hh[(1 * 32 + lane) * 32 + k]);
        wgo[kk] = pack2(       W_hh[(2 * 32 + lane) * 32 + k],
                        0.5f * W_hh[(3 * 32 + lane) * 32 + k]);
    }
    // ---- W_ih i-slice -> registers as gate pairs ----
    u64 wiif[4], wigo[4];
#pragma unroll
    for (int ii = 0; ii < 4; ++ii) {
        const int i = ioff + ii;
        wiif[ii] = pack2(0.5f * W_ih[(0 * 32 + lane) * I_SZ + i],
                         0.5f * W_ih[(1 * 32 + lane) * I_SZ + i]);
        wigo[ii] = pack2(       W_ih[(2 * 32 + lane) * I_SZ + i],
                         0.5f * W_ih[(3 * 32 + lane) * I_SZ + i]);
    }

    // ---- biases: only warp 0's partials carry the bias ----
    u64 bif, bgo;
    if (w == 0) {
        bif = pack2(0.5f * (b_ih[0 * 32 + lane] + b_hh[0 * 32 + lane]),
                    0.5f * (b_ih[1 * 32 + lane] + b_hh[1 * 32 + lane]));
        bgo = pack2(        b_ih[2 * 32 + lane] + b_hh[2 * 32 + lane],
                    0.5f * (b_ih[3 * 32 + lane] + b_hh[3 * 32 + lane]));
    } else {
        bif = 0ull; bgo = 0ull;
    }

    // ---- zero h buffers (warp 0 -> hA, warp 1 -> hB) ----
    {
        u64* hz = w ? hB_sm : hA_sm;
        hz[lane * 2 + 0] = 0ull;
        hz[lane * 2 + 1] = 0ull;
    }

    float c0 = 0.f, c1 = 0.f;     // this warp's 2 batches (2w, 2w+1)
    float h0 = 0.f, h1 = 0.f;

    const float* xw = x + (size_t)blockIdx.x * 4 * T_TOT * I_SZ;
    const int t_ = lane >> 1;            // 0..15
    const int ih = (lane & 1) * 4;       // 0 or 4
    const int aw = 2 * (1 - w);          // away batch base
    u64* const hOwn = w ? hB_sm : hA_sm;
    u64* const exw_if = ex_if + w * 64;
    u64* const exw_go = ex_go + w * 64;
    const u64* const exo_if = ex_if + (1 - w) * 64;
    const u64* const exo_go = ex_go + (1 - w) * 64;

#pragma unroll 1
    for (int tc = 0; tc < NCHUNK; ++tc) {
        __syncthreads();   // prior chunk's x reads complete (and init on tc=0)
        // ---- stage x: warp w loads batches 2w,2w+1; lane covers (t_, ih..ih+3) ----
        {
            const float4 v0 = *(const float4*)(xw
                + ((size_t)(2 * w + 0) * T_TOT + tc * CHUNK + t_) * I_SZ + ih);
            const float4 v1 = *(const float4*)(xw
                + ((size_t)(2 * w + 1) * T_TOT + tc * CHUNK + t_) * I_SZ + ih);
            u64* cell = x_sm + (t_ * I_SZ + ih) * 4 + 2 * w;
            *(ulonglong2*)(cell + 0)  = make_ulonglong2(pack2(v0.x, v0.x), pack2(v1.x, v1.x));
            *(ulonglong2*)(cell + 4)  = make_ulonglong2(pack2(v0.y, v0.y), pack2(v1.y, v1.y));
            *(ulonglong2*)(cell + 8)  = make_ulonglong2(pack2(v0.z, v0.z), pack2(v1.z, v1.z));
            *(ulonglong2*)(cell + 12) = make_ulonglong2(pack2(v0.w, v0.w), pack2(v1.w, v1.w));
        }
        __syncthreads();

#pragma unroll 1
        for (int s = 0; s < CHUNK; ++s) {
            u64 zif[4] = { bif, bif, bif, bif };
            u64 zgo[4] = { bgo, bgo, bgo, bgo };

            // ---- input projection over this warp's i-slice ----
#pragma unroll
            for (int ii = 0; ii < 4; ++ii) {
                const u64* cell = x_sm + (s * I_SZ + ioff + ii) * 4;
                const ulonglong2 x01 = *(const ulonglong2*)(cell + 0);
                const ulonglong2 x23 = *(const ulonglong2*)(cell + 2);
                zif[0] = fma2(x01.x, wiif[ii], zif[0]); zgo[0] = fma2(x01.x, wigo[ii], zgo[0]);
                zif[1] = fma2(x01.y, wiif[ii], zif[1]); zgo[1] = fma2(x01.y, wigo[ii], zgo[1]);
                zif[2] = fma2(x23.x, wiif[ii], zif[2]); zgo[2] = fma2(x23.x, wigo[ii], zgo[2]);
                zif[3] = fma2(x23.y, wiif[ii], zif[3]); zgo[3] = fma2(x23.y, wigo[ii], zgo[3]);
            }

            // ---- recurrent over this warp's k-slice (broadcast dup-h) ----
#pragma unroll
            for (int kk = 0; kk < 16; ++kk) {
                const int k = koff + kk;
                const ulonglong2 h01 = *(const ulonglong2*)(hA_sm + k * 2);
                const ulonglong2 h23 = *(const ulonglong2*)(hB_sm + k * 2);
                zif[0] = fma2(h01.x, wif[kk], zif[0]); zgo[0] = fma2(h01.x, wgo[kk], zgo[0]);
                zif[1] = fma2(h01.y, wif[kk], zif[1]); zgo[1] = fma2(h01.y, wgo[kk], zgo[1]);
                zif[2] = fma2(h23.x, wif[kk], zif[2]); zgo[2] = fma2(h23.x, wgo[kk], zgo[2]);
                zif[3] = fma2(h23.y, wif[kk], zif[3]); zgo[3] = fma2(h23.y, wgo[kk], zgo[3]);
            }

            // ---- exchange away-half partials ----
            *(ulonglong2*)(exw_if + lane * 2) = make_ulonglong2(zif[aw], zif[aw + 1]);
            *(ulonglong2*)(exw_go + lane * 2) = make_ulonglong2(zgo[aw], zgo[aw + 1]);
            __syncthreads();

            const ulonglong2 oif = *(const ulonglong2*)(exo_if + lane * 2);
            const ulonglong2 ogo = *(const ulonglong2*)(exo_go + lane * 2);
            const int ow = 2 * w;
            const u64 zif0 = add2(zif[ow],     oif.x);
            const u64 zif1 = add2(zif[ow + 1], oif.y);
            const u64 zgo0 = add2(zgo[ow],     ogo.x);
            const u64 zgo1 = add2(zgo[ow + 1], ogo.y);

            // ---- activations for this warp's 2 batches ----
            float zi, zf, zg, zo;
            unpack2(zif0, zi, zf); unpack2(zgo0, zg, zo);
            c0 = fmaf(sig_h(zf), c0, sig_h(zi) * tanhap(zg));
            h0 = sig_h(zo) * tanhap(c0);

            unpack2(zif1, zi, zf); unpack2(zgo1, zg, zo);
            c1 = fmaf(sig_h(zf), c1, sig_h(zi) * tanhap(zg));
            h1 = sig_h(zo) * tanhap(c1);

            // ---- publish duplicated h for next step ----
            *(float4*)(hOwn + lane * 2) = make_float4(h0, h0, h1, h1);
            __syncthreads();
        }
    }

    // ---- output head: this warp's 2 batches ----
    const float wo = W_out[lane];
    float v0 = h0 * wo, v1 = h1 * wo;
#pragma unroll
    for (int off = 16; off; off >>= 1) {
        v0 += __shfl_xor_sync(0xffffffffu, v0, off);
        v1 += __shfl_xor_sync(0xffffffffu, v1, off);
    }
    if (lane == 0) {
        const float bout = b_out[0];
        const int bb = blockIdx.x * 4 + 2 * w;
        out[bb + 0] = v0 + bout;
        out[bb + 1] = v1 + bout;
    }
}

extern "C" void kernel_launch(void* const* d_in, const int* in_sizes, int n_in,
                              void* d_out, int out_size)
{
    const float* x     = (const float*)d_in[0];
    const float* W_ih  = (const float*)d_in[1];
    const float* W_hh  = (const float*)d_in[2];
    const float* b_ih  = (const float*)d_in[3];
    const float* b_hh  = (const float*)d_in[4];
    const float* W_out = (const float*)d_in[5];
    const float* b_out = (const float*)d_in[6];
    float* out = (float*)d_out;

    lstm_kernel<<<B_TOT / 4, 64>>>(x, W_ih, W_hh, b_ih, b_hh, W_out, b_out, out);
}

// round 12
// speedup vs baseline: 1.3362x; 1.3362x over previous
#include <cuda_runtime.h>
#include <cstdint>

// LSTM B=4096 T=256 I=8 H=32 O=1.
// Best-of-both composition (R2 inner loop x R10 packaging):
//  - CTA = 32 thr = 1 warp = 4 batch sequences; grid = 1024 -> uniform 6-7
//    warps/SM, no CTA-shape imbalance, reg cap 255.
//  - lane j = hidden unit j. f32x2 lanes are GATE pairs {z_i,z_f},{z_g,z_o}.
//  - W_hh in registers as NATURAL gate pairs {wi,wf}/{wg,wo}: 128 regs total,
//    NO duplication -> no spill -> no LDL traffic in the hot loop.
//  - h and x stored PRE-DUPLICATED ({v,v} u64) in smem: recurrent k-iter =
//    2 broadcast LDS.128 + 8 FFMA2, zero pack instructions.
//  - W_ih gate pairs per-lane in smem (8 iters/step).
//  - tanh.approx activations; sigmoid 0.5 scale folded into i,f,o weights.

#define B_TOT 4096
#define T_TOT 256
#define I_SZ 8
#define CHUNK 16
#define XROW 9          // padded row (in u64-pair units) per t: 8 i + 1 pad

typedef unsigned long long u64;

__device__ __forceinline__ u64 pack2(float a, float b) {
    u64 r; asm("mov.b64 %0,{%1,%2};" : "=l"(r) : "f"(a), "f"(b)); return r;
}
__device__ __forceinline__ void unpack2(u64 v, float& a, float& b) {
    asm("mov.b64 {%0,%1},%2;" : "=f"(a), "=f"(b) : "l"(v));
}
__device__ __forceinline__ u64 fma2(u64 a, u64 b, u64 c) {
    u64 d; asm("fma.rn.f32x2 %0,%1,%2,%3;" : "=l"(d) : "l"(a), "l"(b), "l"(c)); return d;
}
__device__ __forceinline__ float tanhap(float x) {
    float y; asm("tanh.approx.f32 %0,%1;" : "=f"(y) : "f"(x)); return y;
}
// i,f,o accumulators pre-scaled by 0.5: sigmoid(z)=0.5*tanh(z/2)+0.5
__device__ __forceinline__ float sig_h(float zhalf) {
    return fmaf(0.5f, tanhap(zhalf), 0.5f);
}

__global__ void __launch_bounds__(32)
lstm_kernel(const float* __restrict__ x,
            const float* __restrict__ W_ih,
            const float* __restrict__ W_hh,
            const float* __restrict__ b_ih,
            const float* __restrict__ b_hh,
            const float* __restrict__ W_out,
            const float* __restrict__ b_out,
            float* __restrict__ out)
{
    // per-CTA (= per-warp) shared buffers; u64 entries are {v,v} dup pairs
    __shared__ __align__(16) ulonglong2 wi_sm[I_SZ * 32];   // [i][j] {wif},{wgo}
    __shared__ __align__(16) u64 xA[CHUNK * XROW * 2];      // batches 0,1
    __shared__ __align__(16) u64 xB[CHUNK * XROW * 2];      // batches 2,3
    __shared__ __align__(16) u64 hA[2 * 32 * 2];            // [cur][k][b01]
    __shared__ __align__(16) u64 hB[2 * 32 * 2];            // [cur][k][b23]

    const int lane = threadIdx.x & 31;

    // ---- W_hh rows -> registers as natural gate pairs (i,f,o x0.5) ----
    u64 wif[32], wgo[32];
    {
        const float* ri = W_hh + (0 * 32 + lane) * 32;
        const float* rf = W_hh + (1 * 32 + lane) * 32;
        const float* rg = W_hh + (2 * 32 + lane) * 32;
        const float* ro = W_hh + (3 * 32 + lane) * 32;
#pragma unroll
        for (int kk = 0; kk < 8; ++kk) {
            const float4 ai = *(const float4*)(ri + kk * 4);
            const float4 af = *(const float4*)(rf + kk * 4);
            const float4 ag = *(const float4*)(rg + kk * 4);
            const float4 ao = *(const float4*)(ro + kk * 4);
            wif[kk * 4 + 0] = pack2(0.5f * ai.x, 0.5f * af.x);
            wif[kk * 4 + 1] = pack2(0.5f * ai.y, 0.5f * af.y);
            wif[kk * 4 + 2] = pack2(0.5f * ai.z, 0.5f * af.z);
            wif[kk * 4 + 3] = pack2(0.5f * ai.w, 0.5f * af.w);
            wgo[kk * 4 + 0] = pack2(ag.x, 0.5f * ao.x);
            wgo[kk * 4 + 1] = pack2(ag.y, 0.5f * ao.y);
            wgo[kk * 4 + 2] = pack2(ag.z, 0.5f * ao.z);
            wgo[kk * 4 + 3] = pack2(ag.w, 0.5f * ao.w);
        }
    }

    // ---- W_ih gate pairs into smem (per-lane) ----
#pragma unroll
    for (int i = 0; i < I_SZ; ++i) {
        const int j = lane;
        const float a = 0.5f * W_ih[(0 * 32 + j) * I_SZ + i];
        const float b = 0.5f * W_ih[(1 * 32 + j) * I_SZ + i];
        const float c =        W_ih[(2 * 32 + j) * I_SZ + i];
        const float d = 0.5f * W_ih[(3 * 32 + j) * I_SZ + i];
        wi_sm[i * 32 + j] = make_ulonglong2(pack2(a, b), pack2(c, d));
    }

    // ---- zero h buffers ----
#pragma unroll
    for (int q = 0; q < 4; ++q) {
        hA[q * 32 + lane] = 0ull;
        hB[q * 32 + lane] = 0ull;
    }

    // ---- biases (gate pairs, i/f/o pre-scaled) ----
    const float bi_ = 0.5f * (b_ih[0 * 32 + lane] + b_hh[0 * 32 + lane]);
    const float bf_ = 0.5f * (b_ih[1 * 32 + lane] + b_hh[1 * 32 + lane]);
    const float bg_ =         b_ih[2 * 32 + lane] + b_hh[2 * 32 + lane];
    const float bo_ = 0.5f * (b_ih[3 * 32 + lane] + b_hh[3 * 32 + lane]);
    const u64 bif = pack2(bi_, bf_);
    const u64 bgo = pack2(bg_, bo_);

    float c0 = 0.f, c1 = 0.f, c2 = 0.f, c3 = 0.f;
    float h0 = 0.f, h1 = 0.f, h2 = 0.f, h3 = 0.f;
    int cur = 0;

    const float* xw = x + (size_t)blockIdx.x * 4 * T_TOT * I_SZ;
    const int t_ = lane >> 1;
    const int i0 = (lane & 1) * 4;

    __syncwarp();

#pragma unroll 1
    for (int tc = 0; tc < T_TOT / CHUNK; ++tc) {
        // ---- stage x chunk, pre-duplicated {x,x} ----
#pragma unroll
        for (int b = 0; b < 4; ++b) {
            const float4 v = *(const float4*)(xw
                + ((size_t)b * T_TOT + tc * CHUNK + t_) * I_SZ + i0);
            u64* dst = (b < 2) ? xA : xB;
            const int p = b & 1;
            dst[(t_ * XROW + i0 + 0) * 2 + p] = pack2(v.x, v.x);
            dst[(t_ * XROW + i0 + 1) * 2 + p] = pack2(v.y, v.y);
            dst[(t_ * XROW + i0 + 2) * 2 + p] = pack2(v.z, v.z);
            dst[(t_ * XROW + i0 + 3) * 2 + p] = pack2(v.w, v.w);
        }
        __syncwarp();

#pragma unroll 1
        for (int s = 0; s < CHUNK; ++s) {
            const u64* hra = hA + cur * 64;
            const u64* hrb = hB + cur * 64;
            u64*       hwa = hA + (cur ^ 1) * 64;
            u64*       hwb = hB + (cur ^ 1) * 64;

            u64 zif0 = bif, zif1 = bif, zif2 = bif, zif3 = bif;
            u64 zgo0 = bgo, zgo1 = bgo, zgo2 = bgo, zgo3 = bgo;

            // ---- input projection: broadcast dup-x, per-lane smem weights ----
#pragma unroll
            for (int i = 0; i < I_SZ; ++i) {
                const ulonglong2 x01 = *(const ulonglong2*)(xA + (s * XROW + i) * 2);
                const ulonglong2 x23 = *(const ulonglong2*)(xB + (s * XROW + i) * 2);
                const ulonglong2 wv  = wi_sm[i * 32 + lane];
                zif0 = fma2(x01.x, wv.x, zif0); zgo0 = fma2(x01.x, wv.y, zgo0);
                zif1 = fma2(x01.y, wv.x, zif1); zgo1 = fma2(x01.y, wv.y, zgo1);
                zif2 = fma2(x23.x, wv.x, zif2); zgo2 = fma2(x23.x, wv.y, zgo2);
                zif3 = fma2(x23.y, wv.x, zif3); zgo3 = fma2(x23.y, wv.y, zgo3);
            }

            // ---- recurrent: 2 broadcast LDS.128 + 8 fma2 per k, reg weights ----
#pragma unroll
            for (int k = 0; k < 32; ++k) {
                const ulonglong2 h01 = *(const ulonglong2*)(hra + k * 2);
                const ulonglong2 h23 = *(const ulonglong2*)(hrb + k * 2);
                zif0 = fma2(h01.x, wif[k], zif0); zgo0 = fma2(h01.x, wgo[k], zgo0);
                zif1 = fma2(h01.y, wif[k], zif1); zgo1 = fma2(h01.y, wgo[k], zgo1);
                zif2 = fma2(h23.x, wif[k], zif2); zgo2 = fma2(h23.x, wgo[k], zgo2);
                zif3 = fma2(h23.y, wif[k], zif3); zgo3 = fma2(h23.y, wgo[k], zgo3);
            }

            // ---- gates + state update ----
            float zi, zf, zg, zo;

            unpack2(zif0, zi, zf); unpack2(zgo0, zg, zo);
            c0 = fmaf(sig_h(zf), c0, sig_h(zi) * tanhap(zg));
            h0 = sig_h(zo) * tanhap(c0);

            unpack2(zif1, zi, zf); unpack2(zgo1, zg, zo);
            c1 = fmaf(sig_h(zf), c1, sig_h(zi) * tanhap(zg));
            h1 = sig_h(zo) * tanhap(c1);

            unpack2(zif2, zi, zf); unpack2(zgo2, zg, zo);
            c2 = fmaf(sig_h(zf), c2, sig_h(zi) * tanhap(zg));
            h2 = sig_h(zo) * tanhap(c2);

            unpack2(zif3, zi, zf); unpack2(zgo3, zg, zo);
            c3 = fmaf(sig_h(zf), c3, sig_h(zi) * tanhap(zg));
            h3 = sig_h(zo) * tanhap(c3);

            // store duplicated h for next step (conflict-free STS.128)
            *(float4*)(hwa + lane * 2) = make_float4(h0, h0, h1, h1);
            *(float4*)(hwb + lane * 2) = make_float4(h2, h2, h3, h3);
            cur ^= 1;
            __syncwarp();
        }
        __syncwarp();
    }

    // ---- output head: out[b] = sum_j h[b][j]*W_out[j] + b_out ----
    const float wo = W_out[lane];
    float v0 = h0 * wo, v1 = h1 * wo, v2 = h2 * wo, v3 = h3 * wo;
#pragma unroll
    for (int off = 16; off; off >>= 1) {
        v0 += __shfl_xor_sync(0xffffffffu, v0, off);
        v1 += __shfl_xor_sync(0xffffffffu, v1, off);
        v2 += __shfl_xor_sync(0xffffffffu, v2, off);
        v3 += __shfl_xor_sync(0xffffffffu, v3, off);
    }
    if (lane == 0) {
        const float bout = b_out[0];
        const int bb = blockIdx.x * 4;
        out[bb + 0] = v0 + bout;
        out[bb + 1] = v1 + bout;
        out[bb + 2] = v2 + bout;
        out[bb + 3] = v3 + bout;
    }
}

extern "C" void kernel_launch(void* const* d_in, const int* in_sizes, int n_in,
                              void* d_out, int out_size)
{
    const float* x     = (const float*)d_in[0];
    const float* W_ih  = (const float*)d_in[1];
    const float* W_hh  = (const float*)d_in[2];
    const float* b_ih  = (const float*)d_in[3];
    const float* b_hh  = (const float*)d_in[4];
    const float* W_out = (const float*)d_in[5];
    const float* b_out = (const float*)d_in[6];
    float* out = (float*)d_out;

    lstm_kernel<<<B_TOT / 4, 32>>>(x, W_ih, W_hh, b_ih, b_hh, W_out, b_out, out);
}